// round 1
// baseline (speedup 1.0000x reference)
#include <cuda_runtime.h>
#include <math.h>

// Problem constants
#define BB 4
#define CC 64
#define HH 128
#define WW 128
#define OO 64
#define PIX (HH*WW)          // 16384

// Scratch (device globals; no allocation allowed)
__device__ float g_offset[BB*18*PIX];   // ~4.7MB
__device__ float g_mask[BB*9*PIX];      // ~2.4MB
__device__ float g_xt[BB*HH*WW*CC];     // 16MB, NHWC transpose of x

// ---------------------------------------------------------------------------
// Kernel 0: NCHW -> NHWC transpose of x (for coalesced bilinear gathers)
// ---------------------------------------------------------------------------
__global__ void k_transpose(const float* __restrict__ x) {
    __shared__ float s[64*129];
    int h = blockIdx.x, b = blockIdx.y;
    const float* xp = x + ((size_t)b*CC)*PIX + (size_t)h*WW;
    for (int i = threadIdx.x; i < CC*WW; i += blockDim.x) {
        int c = i >> 7, xx = i & 127;
        s[c*129 + xx] = xp[(size_t)c*PIX + xx];
    }
    __syncthreads();
    float* op = g_xt + ((size_t)(b*HH + h)*WW)*CC;
    for (int i = threadIdx.x; i < CC*WW; i += blockDim.x) {
        int xx = i >> 6, c = i & 63;
        op[(size_t)xx*CC + c] = s[c*129 + xx];
    }
}

// ---------------------------------------------------------------------------
// Kernel A: offset + modulator conv.  fea = [x, guide] (128ch) -> 27ch, 3x3, pad 1
// Block: 16x16 output tile, 128 threads (each: 2 horizontally adjacent px, 28 oc)
// smem: weights [9][32][28] (float4 over oc) + fea tile [32][18][20]
// ---------------------------------------------------------------------------
#define WSZ (9*32*28)        // 8064
#define FSZ (32*18*20)       // 11520
#define SMEM_A ((WSZ+FSZ)*4) // 78336 B

__global__ __launch_bounds__(128) void k_offmod(
    const float* __restrict__ x, const float* __restrict__ guide,
    const float* __restrict__ w_off, const float* __restrict__ b_off,
    const float* __restrict__ w_mod, const float* __restrict__ b_mod)
{
    extern __shared__ float sm[];
    float* w_s = sm;            // [kk][ic][28]
    float* f_s = sm + WSZ;      // [ic][18][20]

    int t  = threadIdx.x;
    int bx = blockIdx.x, by = blockIdx.y, b = blockIdx.z;
    int ty  = t >> 3;           // 0..15
    int px0 = (t & 7) << 1;     // 0,2,..,14

    float acc0[28], acc1[28];
#pragma unroll
    for (int i = 0; i < 28; i++) { acc0[i] = 0.f; acc1[i] = 0.f; }

    for (int cc = 0; cc < 4; cc++) {
        __syncthreads();
        // stage weights for this 32-channel chunk
        for (int i = t; i < WSZ; i += 128) {
            int kk = i / (32*28);
            int r  = i % (32*28);
            int ic = r / 28;
            int oc = r % 28;
            int ch = cc*32 + ic;
            float wv = 0.f;
            if (oc < 18)      wv = w_off[(oc*128 + ch)*9 + kk];
            else if (oc < 27) wv = w_mod[((oc-18)*128 + ch)*9 + kk];
            w_s[(kk*32 + ic)*28 + oc] = wv;
        }
        // stage fea tile (18x18 halo, zero pad at borders)
        for (int i = t; i < 32*18*18; i += 128) {
            int ic = i / 324;
            int r  = i % 324;
            int yy = r / 18;
            int xx = r % 18;
            int gyy = by*16 - 1 + yy;
            int gxx = bx*16 - 1 + xx;
            float v = 0.f;
            if (gyy >= 0 && gyy < HH && gxx >= 0 && gxx < WW) {
                int ch = cc*32 + ic;
                const float* src = (ch < 64) ? x : guide;
                int c2 = ch & 63;
                v = src[(((size_t)b*64 + c2)*HH + gyy)*WW + gxx];
            }
            f_s[(ic*18 + yy)*20 + xx] = v;
        }
        __syncthreads();

        for (int ic = 0; ic < 32; ic++) {
            float v[3][4];
#pragma unroll
            for (int ky = 0; ky < 3; ky++)
#pragma unroll
                for (int xi = 0; xi < 4; xi++)
                    v[ky][xi] = f_s[(ic*18 + ty + ky)*20 + px0 + xi];
#pragma unroll
            for (int ky = 0; ky < 3; ky++)
#pragma unroll
            for (int kx = 0; kx < 3; kx++) {
                int kk = ky*3 + kx;
                const float4* wp = (const float4*)&w_s[(kk*32 + ic)*28];
                float va = v[ky][kx], vb = v[ky][kx+1];
#pragma unroll
                for (int j = 0; j < 7; j++) {
                    float4 w4 = wp[j];
                    acc0[j*4+0] += va*w4.x; acc1[j*4+0] += vb*w4.x;
                    acc0[j*4+1] += va*w4.y; acc1[j*4+1] += vb*w4.y;
                    acc0[j*4+2] += va*w4.z; acc1[j*4+2] += vb*w4.z;
                    acc0[j*4+3] += va*w4.w; acc1[j*4+3] += vb*w4.w;
                }
            }
        }
    }

    int gy  = by*16 + ty;
    int gx0 = bx*16 + px0;
    int pix = gy*WW + gx0;
    size_t obase = (size_t)b*18*PIX;
#pragma unroll
    for (int oc = 0; oc < 18; oc++) {
        float bo = b_off[oc];
        g_offset[obase + (size_t)oc*PIX + pix]     = acc0[oc] + bo;
        g_offset[obase + (size_t)oc*PIX + pix + 1] = acc1[oc] + bo;
    }
    size_t mbase = (size_t)b*9*PIX;
#pragma unroll
    for (int oc = 0; oc < 9; oc++) {
        float bm = b_mod[oc];
        float m0 = 2.f / (1.f + expf(-(acc0[18+oc] + bm)));
        float m1 = 2.f / (1.f + expf(-(acc1[18+oc] + bm)));
        g_mask[mbase + (size_t)oc*PIX + pix]     = m0;
        g_mask[mbase + (size_t)oc*PIX + pix + 1] = m1;
    }
}

// ---------------------------------------------------------------------------
// Kernel B: deformable conv. Block = 32 consecutive x-pixels of one row.
// Phase 1: bilinear-sample 32px x 9kk x 64ch into smem (im2col, q = c*9+kk)
// Phase 2: register-blocked GEMM out[64][32] = W[64][576] * vals[576][32]
// smem: vals[32][577] + w chunk [64 q][68 o-padded]
// ---------------------------------------------------------------------------
#define VROW 577
#define SMEM_B ((32*VROW + 64*68)*4)   // 91264 B

__global__ __launch_bounds__(128) void k_deform(
    const float* __restrict__ w_reg, float* __restrict__ out)
{
    extern __shared__ float sm[];
    float* s_vals = sm;               // [32][VROW]
    float* w_s    = sm + 32*VROW;     // [64 q][68]

    int t  = threadIdx.x;
    int b  = blockIdx.z, h = blockIdx.y, w0 = blockIdx.x*32;

    // ---- Phase 1: gather/bilinear -> s_vals ----
    const float4* xbase = (const float4*)(g_xt + (size_t)b*PIX*CC);
    for (int it = 0; it < 36; it++) {
        int j      = it*128 + t;       // 0..4607 = 288 tasks x 16 lanes
        int task   = j >> 4;
        int lane16 = j & 15;
        int kk  = task % 9;
        int pxi = task / 9;
        int w = w0 + pxi;
        int ky = kk / 3, kx = kk - ky*3;
        int pix = h*WW + w;

        float off_y = g_offset[((size_t)(b*18 + 2*kk  ))*PIX + pix];
        float off_x = g_offset[((size_t)(b*18 + 2*kk+1))*PIX + pix];
        float m     = g_mask  [((size_t)(b*9  + kk    ))*PIX + pix];

        float py  = off_y + (float)(ky + h - 1);
        float pxf = off_x + (float)(kx + w - 1);
        float y0f = floorf(py), x0f = floorf(pxf);
        int y0 = (int)y0f, x0 = (int)x0f;
        int y1 = y0 + 1,   x1 = x0 + 1;
        float wy1 = py - y0f,  wx1 = pxf - x0f;
        float wy0 = 1.f - wy1, wx0 = 1.f - wx1;

        bool vy0 = (y0 >= 0 && y0 < HH), vy1 = (y1 >= 0 && y1 < HH);
        bool vx0 = (x0 >= 0 && x0 < WW), vx1 = (x1 >= 0 && x1 < WW);

        float ax = 0.f, ay = 0.f, az = 0.f, aw = 0.f;
        if (vy0 && vx0) { float4 v = xbase[(y0*WW + x0)*16 + lane16]; float g = wy0*wx0;
                          ax += g*v.x; ay += g*v.y; az += g*v.z; aw += g*v.w; }
        if (vy0 && vx1) { float4 v = xbase[(y0*WW + x1)*16 + lane16]; float g = wy0*wx1;
                          ax += g*v.x; ay += g*v.y; az += g*v.z; aw += g*v.w; }
        if (vy1 && vx0) { float4 v = xbase[(y1*WW + x0)*16 + lane16]; float g = wy1*wx0;
                          ax += g*v.x; ay += g*v.y; az += g*v.z; aw += g*v.w; }
        if (vy1 && vx1) { float4 v = xbase[(y1*WW + x1)*16 + lane16]; float g = wy1*wx1;
                          ax += g*v.x; ay += g*v.y; az += g*v.z; aw += g*v.w; }

        int c0 = lane16 << 2;
        float* vp = s_vals + pxi*VROW + kk;
        vp[(c0+0)*9] = ax * m;
        vp[(c0+1)*9] = ay * m;
        vp[(c0+2)*9] = az * m;
        vp[(c0+3)*9] = aw * m;
    }
    __syncthreads();

    // ---- Phase 2: GEMM ----
    int pair = t & 15, ogrp = t >> 4;     // 16 pairs x 8 ogroups
    int px0 = pair*2, px1 = px0 + 1;
    int o0 = ogrp*8;

    float accA[8], accB[8];
#pragma unroll
    for (int i = 0; i < 8; i++) { accA[i] = 0.f; accB[i] = 0.f; }

    for (int qc = 0; qc < 9; qc++) {
        if (qc) __syncthreads();
        // stage weight chunk: w_s[q][o] = w_reg[o][qc*64+q]
        for (int i = t; i < 4096; i += 128) {
            int o = i >> 6, q = i & 63;
            w_s[q*68 + o] = w_reg[(size_t)o*576 + qc*64 + q];
        }
        __syncthreads();

        const float* va = s_vals + px0*VROW + qc*64;
        const float* vb = s_vals + px1*VROW + qc*64;
#pragma unroll 4
        for (int q = 0; q < 64; q++) {
            float v0 = va[q], v1 = vb[q];
            const float4* wp = (const float4*)&w_s[q*68 + o0];
            float4 wA = wp[0], wB = wp[1];
            accA[0] += v0*wA.x; accB[0] += v1*wA.x;
            accA[1] += v0*wA.y; accB[1] += v1*wA.y;
            accA[2] += v0*wA.z; accB[2] += v1*wA.z;
            accA[3] += v0*wA.w; accB[3] += v1*wA.w;
            accA[4] += v0*wB.x; accB[4] += v1*wB.x;
            accA[5] += v0*wB.y; accB[5] += v1*wB.y;
            accA[6] += v0*wB.z; accB[6] += v1*wB.z;
            accA[7] += v0*wB.w; accB[7] += v1*wB.w;
        }
    }

    size_t ob = (size_t)b*64*PIX + (size_t)h*WW;
#pragma unroll
    for (int i = 0; i < 8; i++) {
        out[ob + (size_t)(o0+i)*PIX + w0 + px0] = accA[i];
        out[ob + (size_t)(o0+i)*PIX + w0 + px1] = accB[i];
    }
}

// ---------------------------------------------------------------------------
extern "C" void kernel_launch(void* const* d_in, const int* in_sizes, int n_in,
                              void* d_out, int out_size)
{
    const float* x     = (const float*)d_in[0];
    const float* guide = (const float*)d_in[1];
    const float* w_off = (const float*)d_in[2];
    const float* b_off = (const float*)d_in[3];
    const float* w_mod = (const float*)d_in[4];
    const float* b_mod = (const float*)d_in[5];
    const float* w_reg = (const float*)d_in[6];
    float* out = (float*)d_out;

    cudaFuncSetAttribute(k_offmod, cudaFuncAttributeMaxDynamicSharedMemorySize, SMEM_A);
    cudaFuncSetAttribute(k_deform, cudaFuncAttributeMaxDynamicSharedMemorySize, SMEM_B);

    k_transpose<<<dim3(HH, BB), 256>>>(x);
    k_offmod  <<<dim3(8, 8, BB), 128, SMEM_A>>>(x, guide, w_off, b_off, w_mod, b_mod);
    k_deform  <<<dim3(4, HH, BB), 128, SMEM_B>>>(w_reg, out);
}

// round 2
// speedup vs baseline: 1.0004x; 1.0004x over previous
#include <cuda_runtime.h>
#include <math.h>

// Problem constants
#define BB 4
#define CC 64
#define HH 128
#define WW 128
#define OO 64
#define PIX (HH*WW)          // 16384

// Scratch (device globals; no allocation allowed)
__device__ float g_offset[BB*18*PIX];   // ~4.7MB
__device__ float g_mask[BB*9*PIX];      // ~2.4MB
__device__ float g_xt[BB*HH*WW*CC];     // 16MB, NHWC transpose of x

// ---------------------------------------------------------------------------
// Kernel 0: NCHW -> NHWC transpose of x (for coalesced bilinear gathers)
// ---------------------------------------------------------------------------
__global__ void k_transpose(const float* __restrict__ x) {
    __shared__ float s[64*129];
    int h = blockIdx.x, b = blockIdx.y;
    const float* xp = x + ((size_t)b*CC)*PIX + (size_t)h*WW;
    for (int i = threadIdx.x; i < CC*WW; i += blockDim.x) {
        int c = i >> 7, xx = i & 127;
        s[c*129 + xx] = xp[(size_t)c*PIX + xx];
    }
    __syncthreads();
    float* op = g_xt + ((size_t)(b*HH + h)*WW)*CC;
    for (int i = threadIdx.x; i < CC*WW; i += blockDim.x) {
        int xx = i >> 6, c = i & 63;
        op[(size_t)xx*CC + c] = s[c*129 + xx];
    }
}

// ---------------------------------------------------------------------------
// Kernel A: offset + modulator conv.  fea = [x, guide] (128ch) -> 27ch, 3x3, pad 1
// Block: 16x16 output tile, 128 threads (each: 2 horizontally adjacent px, 28 oc)
// smem: weights [9][32][28] (float4 over oc) + fea tile [32][18][20]
// ---------------------------------------------------------------------------
#define WSZ (9*32*28)        // 8064
#define FSZ (32*18*20)       // 11520
#define SMEM_A ((WSZ+FSZ)*4) // 78336 B

__global__ __launch_bounds__(128) void k_offmod(
    const float* __restrict__ x, const float* __restrict__ guide,
    const float* __restrict__ w_off, const float* __restrict__ b_off,
    const float* __restrict__ w_mod, const float* __restrict__ b_mod)
{
    extern __shared__ float sm[];
    float* w_s = sm;            // [kk][ic][28]
    float* f_s = sm + WSZ;      // [ic][18][20]

    int t  = threadIdx.x;
    int bx = blockIdx.x, by = blockIdx.y, b = blockIdx.z;
    int ty  = t >> 3;           // 0..15
    int px0 = (t & 7) << 1;     // 0,2,..,14

    float acc0[28], acc1[28];
#pragma unroll
    for (int i = 0; i < 28; i++) { acc0[i] = 0.f; acc1[i] = 0.f; }

    for (int cc = 0; cc < 4; cc++) {
        __syncthreads();
        // stage weights for this 32-channel chunk
        for (int i = t; i < WSZ; i += 128) {
            int kk = i / (32*28);
            int r  = i % (32*28);
            int ic = r / 28;
            int oc = r % 28;
            int ch = cc*32 + ic;
            float wv = 0.f;
            if (oc < 18)      wv = w_off[(oc*128 + ch)*9 + kk];
            else if (oc < 27) wv = w_mod[((oc-18)*128 + ch)*9 + kk];
            w_s[(kk*32 + ic)*28 + oc] = wv;
        }
        // stage fea tile (18x18 halo, zero pad at borders)
        for (int i = t; i < 32*18*18; i += 128) {
            int ic = i / 324;
            int r  = i % 324;
            int yy = r / 18;
            int xx = r % 18;
            int gyy = by*16 - 1 + yy;
            int gxx = bx*16 - 1 + xx;
            float v = 0.f;
            if (gyy >= 0 && gyy < HH && gxx >= 0 && gxx < WW) {
                int ch = cc*32 + ic;
                const float* src = (ch < 64) ? x : guide;
                int c2 = ch & 63;
                v = src[(((size_t)b*64 + c2)*HH + gyy)*WW + gxx];
            }
            f_s[(ic*18 + yy)*20 + xx] = v;
        }
        __syncthreads();

        for (int ic = 0; ic < 32; ic++) {
            float v[3][4];
#pragma unroll
            for (int ky = 0; ky < 3; ky++)
#pragma unroll
                for (int xi = 0; xi < 4; xi++)
                    v[ky][xi] = f_s[(ic*18 + ty + ky)*20 + px0 + xi];
#pragma unroll
            for (int ky = 0; ky < 3; ky++)
#pragma unroll
            for (int kx = 0; kx < 3; kx++) {
                int kk = ky*3 + kx;
                const float4* wp = (const float4*)&w_s[(kk*32 + ic)*28];
                float va = v[ky][kx], vb = v[ky][kx+1];
#pragma unroll
                for (int j = 0; j < 7; j++) {
                    float4 w4 = wp[j];
                    acc0[j*4+0] += va*w4.x; acc1[j*4+0] += vb*w4.x;
                    acc0[j*4+1] += va*w4.y; acc1[j*4+1] += vb*w4.y;
                    acc0[j*4+2] += va*w4.z; acc1[j*4+2] += vb*w4.z;
                    acc0[j*4+3] += va*w4.w; acc1[j*4+3] += vb*w4.w;
                }
            }
        }
    }

    int gy  = by*16 + ty;
    int gx0 = bx*16 + px0;
    int pix = gy*WW + gx0;
    size_t obase = (size_t)b*18*PIX;
#pragma unroll
    for (int oc = 0; oc < 18; oc++) {
        float bo = b_off[oc];
        g_offset[obase + (size_t)oc*PIX + pix]     = acc0[oc] + bo;
        g_offset[obase + (size_t)oc*PIX + pix + 1] = acc1[oc] + bo;
    }
    size_t mbase = (size_t)b*9*PIX;
#pragma unroll
    for (int oc = 0; oc < 9; oc++) {
        float bm = b_mod[oc];
        float m0 = 2.f / (1.f + expf(-(acc0[18+oc] + bm)));
        float m1 = 2.f / (1.f + expf(-(acc1[18+oc] + bm)));
        g_mask[mbase + (size_t)oc*PIX + pix]     = m0;
        g_mask[mbase + (size_t)oc*PIX + pix + 1] = m1;
    }
}

// ---------------------------------------------------------------------------
// Kernel B: deformable conv. Block = 32 consecutive x-pixels of one row.
// Phase 1: bilinear-sample 32px x 9kk x 64ch into smem (im2col, q = c*9+kk)
// Phase 2: register-blocked GEMM out[64][32] = W[64][576] * vals[576][32]
// smem: vals[32][577] + w chunk [64 q][68 o-padded]
// ---------------------------------------------------------------------------
#define VROW 577
#define SMEM_B ((32*VROW + 64*68)*4)   // 91264 B

__global__ __launch_bounds__(128) void k_deform(
    const float* __restrict__ w_reg, float* __restrict__ out)
{
    extern __shared__ float sm[];
    float* s_vals = sm;               // [32][VROW]
    float* w_s    = sm + 32*VROW;     // [64 q][68]

    int t  = threadIdx.x;
    int b  = blockIdx.z, h = blockIdx.y, w0 = blockIdx.x*32;

    // ---- Phase 1: gather/bilinear -> s_vals ----
    const float4* xbase = (const float4*)(g_xt + (size_t)b*PIX*CC);
    for (int it = 0; it < 36; it++) {
        int j      = it*128 + t;       // 0..4607 = 288 tasks x 16 lanes
        int task   = j >> 4;
        int lane16 = j & 15;
        int kk  = task % 9;
        int pxi = task / 9;
        int w = w0 + pxi;
        int ky = kk / 3, kx = kk - ky*3;
        int pix = h*WW + w;

        float off_y = g_offset[((size_t)(b*18 + 2*kk  ))*PIX + pix];
        float off_x = g_offset[((size_t)(b*18 + 2*kk+1))*PIX + pix];
        float m     = g_mask  [((size_t)(b*9  + kk    ))*PIX + pix];

        float py  = off_y + (float)(ky + h - 1);
        float pxf = off_x + (float)(kx + w - 1);
        float y0f = floorf(py), x0f = floorf(pxf);
        int y0 = (int)y0f, x0 = (int)x0f;
        int y1 = y0 + 1,   x1 = x0 + 1;
        float wy1 = py - y0f,  wx1 = pxf - x0f;
        float wy0 = 1.f - wy1, wx0 = 1.f - wx1;

        bool vy0 = (y0 >= 0 && y0 < HH), vy1 = (y1 >= 0 && y1 < HH);
        bool vx0 = (x0 >= 0 && x0 < WW), vx1 = (x1 >= 0 && x1 < WW);

        float ax = 0.f, ay = 0.f, az = 0.f, aw = 0.f;
        if (vy0 && vx0) { float4 v = xbase[(y0*WW + x0)*16 + lane16]; float g = wy0*wx0;
                          ax += g*v.x; ay += g*v.y; az += g*v.z; aw += g*v.w; }
        if (vy0 && vx1) { float4 v = xbase[(y0*WW + x1)*16 + lane16]; float g = wy0*wx1;
                          ax += g*v.x; ay += g*v.y; az += g*v.z; aw += g*v.w; }
        if (vy1 && vx0) { float4 v = xbase[(y1*WW + x0)*16 + lane16]; float g = wy1*wx0;
                          ax += g*v.x; ay += g*v.y; az += g*v.z; aw += g*v.w; }
        if (vy1 && vx1) { float4 v = xbase[(y1*WW + x1)*16 + lane16]; float g = wy1*wx1;
                          ax += g*v.x; ay += g*v.y; az += g*v.z; aw += g*v.w; }

        int c0 = lane16 << 2;
        float* vp = s_vals + pxi*VROW + kk;
        vp[(c0+0)*9] = ax * m;
        vp[(c0+1)*9] = ay * m;
        vp[(c0+2)*9] = az * m;
        vp[(c0+3)*9] = aw * m;
    }
    __syncthreads();

    // ---- Phase 2: GEMM ----
    int pair = t & 15, ogrp = t >> 4;     // 16 pairs x 8 ogroups
    int px0 = pair*2, px1 = px0 + 1;
    int o0 = ogrp*8;

    float accA[8], accB[8];
#pragma unroll
    for (int i = 0; i < 8; i++) { accA[i] = 0.f; accB[i] = 0.f; }

    for (int qc = 0; qc < 9; qc++) {
        if (qc) __syncthreads();
        // stage weight chunk: w_s[q][o] = w_reg[o][qc*64+q]
        for (int i = t; i < 4096; i += 128) {
            int o = i >> 6, q = i & 63;
            w_s[q*68 + o] = w_reg[(size_t)o*576 + qc*64 + q];
        }
        __syncthreads();

        const float* va = s_vals + px0*VROW + qc*64;
        const float* vb = s_vals + px1*VROW + qc*64;
#pragma unroll 4
        for (int q = 0; q < 64; q++) {
            float v0 = va[q], v1 = vb[q];
            const float4* wp = (const float4*)&w_s[q*68 + o0];
            float4 wA = wp[0], wB = wp[1];
            accA[0] += v0*wA.x; accB[0] += v1*wA.x;
            accA[1] += v0*wA.y; accB[1] += v1*wA.y;
            accA[2] += v0*wA.z; accB[2] += v1*wA.z;
            accA[3] += v0*wA.w; accB[3] += v1*wA.w;
            accA[4] += v0*wB.x; accB[4] += v1*wB.x;
            accA[5] += v0*wB.y; accB[5] += v1*wB.y;
            accA[6] += v0*wB.z; accB[6] += v1*wB.z;
            accA[7] += v0*wB.w; accB[7] += v1*wB.w;
        }
    }

    size_t ob = (size_t)b*64*PIX + (size_t)h*WW;
#pragma unroll
    for (int i = 0; i < 8; i++) {
        out[ob + (size_t)(o0+i)*PIX + w0 + px0] = accA[i];
        out[ob + (size_t)(o0+i)*PIX + w0 + px1] = accB[i];
    }
}

// ---------------------------------------------------------------------------
extern "C" void kernel_launch(void* const* d_in, const int* in_sizes, int n_in,
                              void* d_out, int out_size)
{
    const float* x     = (const float*)d_in[0];
    const float* guide = (const float*)d_in[1];
    const float* w_off = (const float*)d_in[2];
    const float* b_off = (const float*)d_in[3];
    const float* w_mod = (const float*)d_in[4];
    const float* b_mod = (const float*)d_in[5];
    const float* w_reg = (const float*)d_in[6];
    float* out = (float*)d_out;

    cudaFuncSetAttribute(k_offmod, cudaFuncAttributeMaxDynamicSharedMemorySize, SMEM_A);
    cudaFuncSetAttribute(k_deform, cudaFuncAttributeMaxDynamicSharedMemorySize, SMEM_B);

    k_transpose<<<dim3(HH, BB), 256>>>(x);
    k_offmod  <<<dim3(8, 8, BB), 128, SMEM_A>>>(x, guide, w_off, b_off, w_mod, b_mod);
    k_deform  <<<dim3(4, HH, BB), 128, SMEM_B>>>(w_reg, out);
}

// round 4
// speedup vs baseline: 2.0479x; 2.0470x over previous
#include <cuda_runtime.h>
#include <cuda_bf16.h>
#include <stdint.h>
#include <math.h>

#define BB 4
#define CC 64
#define HH 128
#define WW 128
#define OO 64
#define PIX 16384

// ---------------- device scratch ----------------
__device__ float g_offset[BB*18*PIX];
__device__ float g_mask[BB*9*PIX];
__device__ float g_xt[BB*PIX*CC];     // x NHWC
__device__ float g_gt[BB*PIX*CC];     // guide NHWC
__device__ __nv_bfloat16 g_womh[18*2048];  // offmod B: [chunk][32 oc][64 ch]
__device__ __nv_bfloat16 g_woml[18*2048];
__device__ __nv_bfloat16 g_wrgh[9*4096];   // deform B: [kk][64 oc][64 ch]
__device__ __nv_bfloat16 g_wrgl[9*4096];

// ---------------- helpers ----------------
__device__ __forceinline__ uint32_t smem_u32(const void* p){
    uint32_t a;
    asm("{ .reg .u64 t; cvta.to.shared.u64 t, %1; cvt.u32.u64 %0, t; }" : "=r"(a) : "l"(p));
    return a;
}
__device__ __forceinline__ void ldsm4(uint32_t& r0, uint32_t& r1, uint32_t& r2, uint32_t& r3, uint32_t a){
    asm volatile("ldmatrix.sync.aligned.m8n8.x4.shared.b16 {%0,%1,%2,%3}, [%4];"
                 : "=r"(r0),"=r"(r1),"=r"(r2),"=r"(r3) : "r"(a));
}
__device__ __forceinline__ void mma16816(float* d, uint32_t a0, uint32_t a1, uint32_t a2, uint32_t a3,
                                         uint32_t b0, uint32_t b1){
    asm volatile("mma.sync.aligned.m16n8k16.row.col.f32.bf16.bf16.f32 "
                 "{%0,%1,%2,%3}, {%4,%5,%6,%7}, {%8,%9}, {%0,%1,%2,%3};"
                 : "+f"(d[0]),"+f"(d[1]),"+f"(d[2]),"+f"(d[3])
                 : "r"(a0),"r"(a1),"r"(a2),"r"(a3),"r"(b0),"r"(b1));
}
__device__ __forceinline__ void sts4(uint32_t a, uint32_t x, uint32_t y, uint32_t z, uint32_t w){
    asm volatile("st.shared.v4.u32 [%0], {%1,%2,%3,%4};" :: "r"(a),"r"(x),"r"(y),"r"(z),"r"(w) : "memory");
}
__device__ __forceinline__ void sts2(uint32_t a, uint32_t x, uint32_t y){
    asm volatile("st.shared.v2.u32 [%0], {%1,%2};" :: "r"(a),"r"(x),"r"(y) : "memory");
}
__device__ __forceinline__ uint32_t pk(float lo_e, float hi_e){
    uint32_t r;
    asm("cvt.rn.bf16x2.f32 %0, %1, %2;" : "=r"(r) : "f"(hi_e), "f"(lo_e));
    return r;
}
__device__ __forceinline__ float btrunc(float v){ return __bfloat162float(__float2bfloat16(v)); }

// ---------------------------------------------------------------------------
// Kernel 0: NCHW -> NHWC transpose (x and guide)
// ---------------------------------------------------------------------------
__global__ void k_transpose(const float* __restrict__ x, const float* __restrict__ g){
    __shared__ float s[64*129];
    int h = blockIdx.x, b = blockIdx.y;
    const float* src = blockIdx.z ? g : x;
    float* dst       = blockIdx.z ? g_gt : g_xt;
    const float* xp = src + ((size_t)b*CC)*PIX + (size_t)h*WW;
    for (int i = threadIdx.x; i < CC*WW; i += blockDim.x) {
        int c = i >> 7, xx = i & 127;
        s[c*129 + xx] = xp[(size_t)c*PIX + xx];
    }
    __syncthreads();
    float* op = dst + ((size_t)(b*HH + h)*WW)*CC;
    for (int i = threadIdx.x; i < CC*WW; i += blockDim.x) {
        int xx = i >> 6, c = i & 63;
        op[(size_t)xx*CC + c] = s[c*129 + xx];
    }
}

// ---------------------------------------------------------------------------
// Kernel 1: weight prep — fp32 -> bf16 hi/lo
// ---------------------------------------------------------------------------
__global__ void k_prepw(const float* __restrict__ w_off, const float* __restrict__ w_mod,
                        const float* __restrict__ w_reg){
    int i = blockIdx.x*256 + threadIdx.x;
    if (i < 36864) {
        // offmod: chunk = kk*2+half, [32 oc (27 real)][64 ch]
        int chunk = i >> 11; int r = i & 2047; int n = r >> 6; int c = r & 63;
        int kk = chunk >> 1, half = chunk & 1, ch = half*64 + c;
        float w = 0.f;
        if (n < 18)      w = w_off[(n*128 + ch)*9 + kk];
        else if (n < 27) w = w_mod[((n-18)*128 + ch)*9 + kk];
        __nv_bfloat16 hb = __float2bfloat16(w);
        g_womh[i] = hb;
        g_woml[i] = __float2bfloat16(w - __bfloat162float(hb));
        // deform: [kk][64 oc][64 ch]
        int kk2 = i >> 12; int n2 = (i & 4095) >> 6; int c2 = i & 63;
        float w2 = w_reg[(n2*64 + c2)*9 + kk2];
        __nv_bfloat16 hb2 = __float2bfloat16(w2);
        g_wrgh[i] = hb2;
        g_wrgl[i] = __float2bfloat16(w2 - __bfloat162float(hb2));
    }
}

// ---------------------------------------------------------------------------
// Kernel 2: offset+modulator conv (M=128 row, N=32(27), K=1152) via mma.sync
// smem rows padded to 144B (72 bf16) for conflict-free ldmatrix
// ---------------------------------------------------------------------------
#define OM_AH 0
#define OM_AL 18432
#define OM_BH 36864
#define OM_BL 41472
#define OM_SMEM (46080 + 128)

__global__ __launch_bounds__(128) void k_offmod(const float* __restrict__ b_off,
                                                const float* __restrict__ b_mod)
{
    extern __shared__ char smem_raw[];
    uint32_t sbr = smem_u32(smem_raw);
    uint32_t sb  = (sbr + 127) & ~127u;
    char* sm0 = smem_raw + (sb - sbr);

    int t = threadIdx.x, wid = t >> 5, lid = t & 31;
    int h = blockIdx.x, b = blockIdx.y;

    uint32_t aRowSel = (lid & 7) + ((lid >> 3) & 1) * 8;
    uint32_t aColSel = ((lid >> 4) & 1) * 16;
    uint32_t bRowSel = (lid & 7) + ((lid >> 4) & 1) * 8;
    uint32_t bColSel = ((lid >> 3) & 1) * 16;

    float acc[32];
#pragma unroll
    for (int i = 0; i < 32; i++) acc[i] = 0.f;

    for (int chunk = 0; chunk < 18; chunk++) {
        int kk = chunk >> 1, half = chunk & 1;
        int dy = kk/3 - 1, dx = kk%3 - 1;
        __syncthreads();
        { // stage B: 32 rows x 128B (+16B pad), hi & lo
            const float4* wh = (const float4*)(g_womh + chunk*2048);
            const float4* wl = (const float4*)(g_woml + chunk*2048);
#pragma unroll
            for (int j = t; j < 256; j += 128) {
                int row = j >> 3, seg = j & 7;
                *(float4*)(sm0 + OM_BH + row*144 + seg*16) = wh[j];
                *(float4*)(sm0 + OM_BL + row*144 + seg*16) = wl[j];
            }
        }
        { // stage A: [128 px][64 ch] of x/guide (NHWC) at (h+dy, px+dx)
            int hy = h + dy;
            bool rowok = (hy >= 0) && (hy < HH);
            const float* rowp = (half ? g_gt : g_xt) + (((size_t)b*HH + (rowok?hy:0))*WW)*CC;
#pragma unroll
            for (int jj = 0; jj < 8; jj++) {
                int i = jj*128 + t;
                int px = i >> 3, c8 = i & 7;
                int gx = px + dx;
                float v0=0,v1=0,v2=0,v3=0,v4=0,v5=0,v6=0,v7=0;
                if (rowok && gx >= 0 && gx < WW) {
                    const float4* p = (const float4*)(rowp + (size_t)gx*CC + c8*8);
                    float4 a = p[0], c = p[1];
                    v0=a.x; v1=a.y; v2=a.z; v3=a.w; v4=c.x; v5=c.y; v6=c.z; v7=c.w;
                }
                float w0=btrunc(v0),w1=btrunc(v1),w2=btrunc(v2),w3=btrunc(v3);
                float w4=btrunc(v4),w5=btrunc(v5),w6=btrunc(v6),w7=btrunc(v7);
                uint32_t off = px*144 + c8*16;
                sts4(sb + OM_AH + off, pk(v0,v1), pk(v2,v3), pk(v4,v5), pk(v6,v7));
                sts4(sb + OM_AL + off, pk(v0-w0,v1-w1), pk(v2-w2,v3-w3),
                                       pk(v4-w4,v5-w5), pk(v6-w6,v7-w7));
            }
        }
        __syncthreads();

#pragma unroll
        for (int ks = 0; ks < 4; ks++) {
            uint32_t kcol = ks*32;
            uint32_t bh[8], bl[8], ah[8], al[8];
#pragma unroll
            for (int p = 0; p < 2; p++) {
                uint32_t ba = sb + OM_BH + (p*16 + bRowSel)*144 + kcol + bColSel;
                ldsm4(bh[p*4+0], bh[p*4+1], bh[p*4+2], bh[p*4+3], ba);
                ldsm4(bl[p*4+0], bl[p*4+1], bl[p*4+2], bl[p*4+3], ba + (OM_BL-OM_BH));
            }
#pragma unroll
            for (int m = 0; m < 2; m++) {
                uint32_t aa = sb + OM_AH + (wid*32 + m*16 + aRowSel)*144 + kcol + aColSel;
                ldsm4(ah[m*4+0], ah[m*4+1], ah[m*4+2], ah[m*4+3], aa);
                ldsm4(al[m*4+0], al[m*4+1], al[m*4+2], al[m*4+3], aa + (OM_AL-OM_AH));
            }
#pragma unroll
            for (int m = 0; m < 2; m++)
#pragma unroll
            for (int n = 0; n < 4; n++) {
                float* d = acc + (m*4+n)*4;
                uint32_t i0 = (n>>1)*4 + (n&1)*2;
                mma16816(d, ah[m*4+0],ah[m*4+1],ah[m*4+2],ah[m*4+3], bh[i0], bh[i0+1]);
                mma16816(d, al[m*4+0],al[m*4+1],al[m*4+2],al[m*4+3], bh[i0], bh[i0+1]);
                mma16816(d, ah[m*4+0],ah[m*4+1],ah[m*4+2],ah[m*4+3], bl[i0], bl[i0+1]);
            }
        }
    }

    // epilogue
    int g = lid >> 2, tig = lid & 3;
    int pixbase = h*WW;
#pragma unroll
    for (int m = 0; m < 2; m++)
#pragma unroll
    for (int n = 0; n < 4; n++)
#pragma unroll
    for (int r = 0; r < 4; r++) {
        int px = wid*32 + m*16 + g + (r>>1)*8;
        int oc = n*8 + 2*tig + (r&1);
        float v = acc[(m*4+n)*4 + r];
        int pix = pixbase + px;
        if (oc < 18) {
            g_offset[(size_t)(b*18 + oc)*PIX + pix] = v + b_off[oc];
        } else if (oc < 27) {
            float z = v + b_mod[oc-18];
            g_mask[(size_t)(b*9 + oc-18)*PIX + pix] = 2.f / (1.f + expf(-z));
        }
    }
}

// ---------------------------------------------------------------------------
// Kernel 3: deformable conv (M=128 row, N=64, K=576) via mma.sync
// ---------------------------------------------------------------------------
#define DF_AH 0
#define DF_AL 18432
#define DF_BH 36864
#define DF_BL 46080
#define DF_PR 55296
#define DF_SMEM (59392 + 128)

__global__ __launch_bounds__(128) void k_deform(float* __restrict__ out)
{
    extern __shared__ char smem_raw[];
    uint32_t sbr = smem_u32(smem_raw);
    uint32_t sb  = (sbr + 127) & ~127u;
    char* sm0 = smem_raw + (sb - sbr);
    int*   spi = (int*)(sm0 + DF_PR);
    float* spf = (float*)(sm0 + DF_PR);

    int t = threadIdx.x, wid = t >> 5, lid = t & 31;
    int h = blockIdx.x, b = blockIdx.y;

    uint32_t aRowSel = (lid & 7) + ((lid >> 3) & 1) * 8;
    uint32_t aColSel = ((lid >> 4) & 1) * 16;
    uint32_t bRowSel = (lid & 7) + ((lid >> 4) & 1) * 8;
    uint32_t bColSel = ((lid >> 3) & 1) * 16;

    const float4* xb4 = (const float4*)(g_xt + (size_t)b*PIX*CC);

    float acc[64];
#pragma unroll
    for (int i = 0; i < 64; i++) acc[i] = 0.f;

    for (int kk = 0; kk < 9; kk++) {
        __syncthreads();
        { // stage B: 64 rows x 128B (+16B pad), hi & lo
            const float4* wh = (const float4*)(g_wrgh + kk*4096);
            const float4* wl = (const float4*)(g_wrgl + kk*4096);
#pragma unroll
            for (int j = t; j < 512; j += 128) {
                int row = j >> 3, seg = j & 7;
                *(float4*)(sm0 + DF_BH + row*144 + seg*16) = wh[j];
                *(float4*)(sm0 + DF_BL + row*144 + seg*16) = wl[j];
            }
        }
        { // per-px bilinear params (t == px)
            int px = t;
            int pix = h*WW + px;
            float off_y = g_offset[((size_t)(b*18 + 2*kk  ))*PIX + pix];
            float off_x = g_offset[((size_t)(b*18 + 2*kk+1))*PIX + pix];
            float m     = g_mask  [((size_t)(b*9  + kk    ))*PIX + pix];
            int ky = kk/3, kx = kk - ky*3;
            float py  = off_y + (float)(ky + h - 1);
            float pxf = off_x + (float)(kx + px - 1);
            float y0f = floorf(py), x0f = floorf(pxf);
            int y0 = (int)y0f, x0 = (int)x0f;
            int y1 = y0 + 1,   x1 = x0 + 1;
            float wy1 = py - y0f,  wx1 = pxf - x0f;
            float wy0 = 1.f - wy1, wx0 = 1.f - wx1;
            bool vy0 = (y0>=0 && y0<HH), vy1 = (y1>=0 && y1<HH);
            bool vx0 = (x0>=0 && x0<WW), vx1 = (x1>=0 && x1<WW);
            int y0c = min(max(y0,0),HH-1), y1c = min(max(y1,0),HH-1);
            int x0c = min(max(x0,0),WW-1), x1c = min(max(x1,0),WW-1);
            int base = px*8;
            spi[base+0] = (y0c*WW + x0c)*16;
            spi[base+1] = (y0c*WW + x1c)*16;
            spi[base+2] = (y1c*WW + x0c)*16;
            spi[base+3] = (y1c*WW + x1c)*16;
            spf[base+4] = (vy0&&vx0) ? wy0*wx0*m : 0.f;
            spf[base+5] = (vy0&&vx1) ? wy0*wx1*m : 0.f;
            spf[base+6] = (vy1&&vx0) ? wy1*wx0*m : 0.f;
            spf[base+7] = (vy1&&vx1) ? wy1*wx1*m : 0.f;
        }
        __syncthreads();
        // gather: 128px x 16 lanes (4 ch each)
#pragma unroll 2
        for (int it = 0; it < 16; it++) {
            int j = it*128 + t;
            int px = j >> 4, lane16 = j & 15;
            int base = px*8;
            int i00 = spi[base+0], i01 = spi[base+1], i10 = spi[base+2], i11 = spi[base+3];
            float g00 = spf[base+4], g01 = spf[base+5], g10 = spf[base+6], g11 = spf[base+7];
            float4 a = xb4[i00 + lane16];
            float4 c = xb4[i01 + lane16];
            float4 d = xb4[i10 + lane16];
            float4 e = xb4[i11 + lane16];
            float v0 = g00*a.x + g01*c.x + g10*d.x + g11*e.x;
            float v1 = g00*a.y + g01*c.y + g10*d.y + g11*e.y;
            float v2 = g00*a.z + g01*c.z + g10*d.z + g11*e.z;
            float v3 = g00*a.w + g01*c.w + g10*d.w + g11*e.w;
            float w0=btrunc(v0), w1=btrunc(v1), w2=btrunc(v2), w3=btrunc(v3);
            uint32_t off = px*144 + lane16*8;
            sts2(sb + DF_AH + off, pk(v0,v1), pk(v2,v3));
            sts2(sb + DF_AL + off, pk(v0-w0,v1-w1), pk(v2-w2,v3-w3));
        }
        __syncthreads();

#pragma unroll
        for (int ks = 0; ks < 4; ks++) {
            uint32_t kcol = ks*32;
            uint32_t bh[16], bl[16], ah[8], al[8];
#pragma unroll
            for (int p = 0; p < 4; p++) {
                uint32_t ba = sb + DF_BH + (p*16 + bRowSel)*144 + kcol + bColSel;
                ldsm4(bh[p*4+0], bh[p*4+1], bh[p*4+2], bh[p*4+3], ba);
                ldsm4(bl[p*4+0], bl[p*4+1], bl[p*4+2], bl[p*4+3], ba + (DF_BL-DF_BH));
            }
#pragma unroll
            for (int m = 0; m < 2; m++) {
                uint32_t aa = sb + DF_AH + (wid*32 + m*16 + aRowSel)*144 + kcol + aColSel;
                ldsm4(ah[m*4+0], ah[m*4+1], ah[m*4+2], ah[m*4+3], aa);
                ldsm4(al[m*4+0], al[m*4+1], al[m*4+2], al[m*4+3], aa + (DF_AL-DF_AH));
            }
#pragma unroll
            for (int m = 0; m < 2; m++)
#pragma unroll
            for (int n = 0; n < 8; n++) {
                float* d = acc + (m*8+n)*4;
                uint32_t i0 = (n>>1)*4 + (n&1)*2;
                mma16816(d, ah[m*4+0],ah[m*4+1],ah[m*4+2],ah[m*4+3], bh[i0], bh[i0+1]);
                mma16816(d, al[m*4+0],al[m*4+1],al[m*4+2],al[m*4+3], bh[i0], bh[i0+1]);
                mma16816(d, ah[m*4+0],ah[m*4+1],ah[m*4+2],ah[m*4+3], bl[i0], bl[i0+1]);
            }
        }
    }

    // epilogue
    int g = lid >> 2, tig = lid & 3;
    size_t ob = (size_t)b*64*PIX + (size_t)h*WW;
#pragma unroll
    for (int m = 0; m < 2; m++)
#pragma unroll
    for (int n = 0; n < 8; n++)
#pragma unroll
    for (int r = 0; r < 4; r++) {
        int px = wid*32 + m*16 + g + (r>>1)*8;
        int oc = n*8 + 2*tig + (r&1);
        out[ob + (size_t)oc*PIX + px] = acc[(m*8+n)*4 + r];
    }
}

// ---------------------------------------------------------------------------
extern "C" void kernel_launch(void* const* d_in, const int* in_sizes, int n_in,
                              void* d_out, int out_size)
{
    const float* x     = (const float*)d_in[0];
    const float* guide = (const float*)d_in[1];
    const float* w_off = (const float*)d_in[2];
    const float* b_off = (const float*)d_in[3];
    const float* w_mod = (const float*)d_in[4];
    const float* b_mod = (const float*)d_in[5];
    const float* w_reg = (const float*)d_in[6];
    float* out = (float*)d_out;

    cudaFuncSetAttribute(k_offmod, cudaFuncAttributeMaxDynamicSharedMemorySize, OM_SMEM);
    cudaFuncSetAttribute(k_deform, cudaFuncAttributeMaxDynamicSharedMemorySize, DF_SMEM);

    k_transpose<<<dim3(HH, BB, 2), 256>>>(x, guide);
    k_prepw    <<<144, 256>>>(w_off, w_mod, w_reg);
    k_offmod   <<<dim3(HH, BB), 128, OM_SMEM>>>(b_off, b_mod);
    k_deform   <<<dim3(HH, BB), 128, DF_SMEM>>>(out);
}

// round 5
// speedup vs baseline: 2.7240x; 1.3302x over previous
#include <cuda_runtime.h>
#include <cuda_bf16.h>
#include <stdint.h>
#include <math.h>

#define BB 4
#define CC 64
#define HH 128
#define WW 128
#define OO 64
#define PIX 16384

// ---------------- device scratch ----------------
__device__ float g_offset[BB*18*PIX];
__device__ float g_mask[BB*9*PIX];
__device__ float g_xt[BB*PIX*CC];     // x NHWC
__device__ float g_gt[BB*PIX*CC];     // guide NHWC
__device__ __nv_bfloat16 g_womh[18*2048];  // offmod B: [chunk][32 oc][64 ch]
__device__ __nv_bfloat16 g_woml[18*2048];
__device__ __nv_bfloat16 g_wrgh[9*4096];   // deform B: [kk][64 oc][64 ch]
__device__ __nv_bfloat16 g_wrgl[9*4096];

// ---------------- helpers ----------------
__device__ __forceinline__ uint32_t smem_u32(const void* p){
    uint32_t a;
    asm("{ .reg .u64 t; cvta.to.shared.u64 t, %1; cvt.u32.u64 %0, t; }" : "=r"(a) : "l"(p));
    return a;
}
__device__ __forceinline__ void ldsm4(uint32_t& r0, uint32_t& r1, uint32_t& r2, uint32_t& r3, uint32_t a){
    asm volatile("ldmatrix.sync.aligned.m8n8.x4.shared.b16 {%0,%1,%2,%3}, [%4];"
                 : "=r"(r0),"=r"(r1),"=r"(r2),"=r"(r3) : "r"(a));
}
__device__ __forceinline__ void mma16816(float* d, uint32_t a0, uint32_t a1, uint32_t a2, uint32_t a3,
                                         uint32_t b0, uint32_t b1){
    asm volatile("mma.sync.aligned.m16n8k16.row.col.f32.bf16.bf16.f32 "
                 "{%0,%1,%2,%3}, {%4,%5,%6,%7}, {%8,%9}, {%0,%1,%2,%3};"
                 : "+f"(d[0]),"+f"(d[1]),"+f"(d[2]),"+f"(d[3])
                 : "r"(a0),"r"(a1),"r"(a2),"r"(a3),"r"(b0),"r"(b1));
}
__device__ __forceinline__ void sts4(uint32_t a, uint32_t x, uint32_t y, uint32_t z, uint32_t w){
    asm volatile("st.shared.v4.u32 [%0], {%1,%2,%3,%4};" :: "r"(a),"r"(x),"r"(y),"r"(z),"r"(w) : "memory");
}
__device__ __forceinline__ void sts2(uint32_t a, uint32_t x, uint32_t y){
    asm volatile("st.shared.v2.u32 [%0], {%1,%2};" :: "r"(a),"r"(x),"r"(y) : "memory");
}
__device__ __forceinline__ uint32_t pk(float lo_e, float hi_e){
    uint32_t r;
    asm("cvt.rn.bf16x2.f32 %0, %1, %2;" : "=r"(r) : "f"(hi_e), "f"(lo_e));
    return r;
}
__device__ __forceinline__ float btrunc(float v){ return __bfloat162float(__float2bfloat16(v)); }

// ---------------------------------------------------------------------------
// Kernel 0: NCHW -> NHWC transpose (x and guide)
// ---------------------------------------------------------------------------
__global__ void k_transpose(const float* __restrict__ x, const float* __restrict__ g){
    __shared__ float s[64*129];
    int h = blockIdx.x, b = blockIdx.y;
    const float* src = blockIdx.z ? g : x;
    float* dst       = blockIdx.z ? g_gt : g_xt;
    const float* xp = src + ((size_t)b*CC)*PIX + (size_t)h*WW;
    for (int i = threadIdx.x; i < CC*WW; i += blockDim.x) {
        int c = i >> 7, xx = i & 127;
        s[c*129 + xx] = xp[(size_t)c*PIX + xx];
    }
    __syncthreads();
    float* op = dst + ((size_t)(b*HH + h)*WW)*CC;
    for (int i = threadIdx.x; i < CC*WW; i += blockDim.x) {
        int xx = i >> 6, c = i & 63;
        op[(size_t)xx*CC + c] = s[c*129 + xx];
    }
}

// ---------------------------------------------------------------------------
// Kernel 1: weight prep — fp32 -> bf16 hi/lo
// ---------------------------------------------------------------------------
__global__ void k_prepw(const float* __restrict__ w_off, const float* __restrict__ w_mod,
                        const float* __restrict__ w_reg){
    int i = blockIdx.x*256 + threadIdx.x;
    if (i < 36864) {
        int chunk = i >> 11; int r = i & 2047; int n = r >> 6; int c = r & 63;
        int kk = chunk >> 1, half = chunk & 1, ch = half*64 + c;
        float w = 0.f;
        if (n < 18)      w = w_off[(n*128 + ch)*9 + kk];
        else if (n < 27) w = w_mod[((n-18)*128 + ch)*9 + kk];
        __nv_bfloat16 hb = __float2bfloat16(w);
        g_womh[i] = hb;
        g_woml[i] = __float2bfloat16(w - __bfloat162float(hb));
        int kk2 = i >> 12; int n2 = (i & 4095) >> 6; int c2 = i & 63;
        float w2 = w_reg[(n2*64 + c2)*9 + kk2];
        __nv_bfloat16 hb2 = __float2bfloat16(w2);
        g_wrgh[i] = hb2;
        g_wrgl[i] = __float2bfloat16(w2 - __bfloat162float(hb2));
    }
}

// ---------------------------------------------------------------------------
// Kernel 2: offset+modulator conv (M=128 row, N=32(27), K=1152) via mma.sync
// 256 threads: warp = (mwid 0..3 [M=32], nhalf 0..1 [N=16])
// ---------------------------------------------------------------------------
#define OM_AH 0
#define OM_AL 18432
#define OM_BH 36864
#define OM_BL 41472
#define OM_SMEM (46080 + 128)

__global__ __launch_bounds__(256) void k_offmod(const float* __restrict__ b_off,
                                                const float* __restrict__ b_mod)
{
    extern __shared__ char smem_raw[];
    uint32_t sbr = smem_u32(smem_raw);
    uint32_t sb  = (sbr + 127) & ~127u;
    char* sm0 = smem_raw + (sb - sbr);

    int t = threadIdx.x, wid = t >> 5, lid = t & 31;
    int mwid = wid & 3, nhalf = wid >> 2;
    int h = blockIdx.x, b = blockIdx.y;

    uint32_t aRowSel = (lid & 7) + ((lid >> 3) & 1) * 8;
    uint32_t aColSel = ((lid >> 4) & 1) * 16;
    uint32_t bRowSel = (lid & 7) + ((lid >> 4) & 1) * 8;
    uint32_t bColSel = ((lid >> 3) & 1) * 16;

    float acc[16];
#pragma unroll
    for (int i = 0; i < 16; i++) acc[i] = 0.f;

    for (int chunk = 0; chunk < 18; chunk++) {
        int kk = chunk >> 1, half = chunk & 1;
        int dy = kk/3 - 1, dx = kk%3 - 1;
        __syncthreads();
        { // stage B: 32 rows x 128B (+16B pad), hi & lo — 256 items over 256 thr
            const float4* wh = (const float4*)(g_womh + chunk*2048);
            const float4* wl = (const float4*)(g_woml + chunk*2048);
            int row = t >> 3, seg = t & 7;
            *(float4*)(sm0 + OM_BH + row*144 + seg*16) = wh[t];
            *(float4*)(sm0 + OM_BL + row*144 + seg*16) = wl[t];
        }
        { // stage A: [128 px][64 ch] of x/guide (NHWC) at (h+dy, px+dx)
            int hy = h + dy;
            bool rowok = (hy >= 0) && (hy < HH);
            const float* rowp = (half ? g_gt : g_xt) + (((size_t)b*HH + (rowok?hy:0))*WW)*CC;
#pragma unroll
            for (int jj = 0; jj < 4; jj++) {
                int i = jj*256 + t;
                int px = i >> 3, c8 = i & 7;
                int gx = px + dx;
                float v0=0,v1=0,v2=0,v3=0,v4=0,v5=0,v6=0,v7=0;
                if (rowok && gx >= 0 && gx < WW) {
                    const float4* p = (const float4*)(rowp + (size_t)gx*CC + c8*8);
                    float4 a = p[0], c = p[1];
                    v0=a.x; v1=a.y; v2=a.z; v3=a.w; v4=c.x; v5=c.y; v6=c.z; v7=c.w;
                }
                float w0=btrunc(v0),w1=btrunc(v1),w2=btrunc(v2),w3=btrunc(v3);
                float w4=btrunc(v4),w5=btrunc(v5),w6=btrunc(v6),w7=btrunc(v7);
                uint32_t off = px*144 + c8*16;
                sts4(sb + OM_AH + off, pk(v0,v1), pk(v2,v3), pk(v4,v5), pk(v6,v7));
                sts4(sb + OM_AL + off, pk(v0-w0,v1-w1), pk(v2-w2,v3-w3),
                                       pk(v4-w4,v5-w5), pk(v6-w6,v7-w7));
            }
        }
        __syncthreads();

#pragma unroll
        for (int ks = 0; ks < 4; ks++) {
            uint32_t kcol = ks*32;
            uint32_t bh[4], bl[4], ah[8], al[8];
            uint32_t ba = sb + OM_BH + (nhalf*16 + bRowSel)*144 + kcol + bColSel;
            ldsm4(bh[0], bh[1], bh[2], bh[3], ba);
            ldsm4(bl[0], bl[1], bl[2], bl[3], ba + (OM_BL-OM_BH));
#pragma unroll
            for (int m = 0; m < 2; m++) {
                uint32_t aa = sb + OM_AH + (mwid*32 + m*16 + aRowSel)*144 + kcol + aColSel;
                ldsm4(ah[m*4+0], ah[m*4+1], ah[m*4+2], ah[m*4+3], aa);
                ldsm4(al[m*4+0], al[m*4+1], al[m*4+2], al[m*4+3], aa + (OM_AL-OM_AH));
            }
#pragma unroll
            for (int m = 0; m < 2; m++)
#pragma unroll
            for (int n = 0; n < 2; n++) {
                float* d = acc + (m*2+n)*4;
                uint32_t i0 = n*2;
                mma16816(d, ah[m*4+0],ah[m*4+1],ah[m*4+2],ah[m*4+3], bh[i0], bh[i0+1]);
                mma16816(d, al[m*4+0],al[m*4+1],al[m*4+2],al[m*4+3], bh[i0], bh[i0+1]);
                mma16816(d, ah[m*4+0],ah[m*4+1],ah[m*4+2],ah[m*4+3], bl[i0], bl[i0+1]);
            }
        }
    }

    // epilogue
    int g = lid >> 2, tig = lid & 3;
    int pixbase = h*WW;
#pragma unroll
    for (int m = 0; m < 2; m++)
#pragma unroll
    for (int n = 0; n < 2; n++)
#pragma unroll
    for (int r = 0; r < 4; r++) {
        int px = mwid*32 + m*16 + g + (r>>1)*8;
        int oc = nhalf*16 + n*8 + 2*tig + (r&1);
        float v = acc[(m*2+n)*4 + r];
        int pix = pixbase + px;
        if (oc < 18) {
            g_offset[(size_t)(b*18 + oc)*PIX + pix] = v + b_off[oc];
        } else if (oc < 27) {
            float z = v + b_mod[oc-18];
            g_mask[(size_t)(b*9 + oc-18)*PIX + pix] = 2.f / (1.f + expf(-z));
        }
    }
}

// ---------------------------------------------------------------------------
// Kernel 3: deformable conv (M=128 row, N=64, K=576) via mma.sync
// 256 threads: warp = (mwid 0..3 [M=32], nhalf 0..1 [N=32])
// ---------------------------------------------------------------------------
#define DF_AH 0
#define DF_AL 18432
#define DF_BH 36864
#define DF_BL 46080
#define DF_PR 55296
#define DF_SMEM (59392 + 128)

__global__ __launch_bounds__(256) void k_deform(float* __restrict__ out)
{
    extern __shared__ char smem_raw[];
    uint32_t sbr = smem_u32(smem_raw);
    uint32_t sb  = (sbr + 127) & ~127u;
    char* sm0 = smem_raw + (sb - sbr);
    int*   spi = (int*)(sm0 + DF_PR);
    float* spf = (float*)(sm0 + DF_PR);

    int t = threadIdx.x, wid = t >> 5, lid = t & 31;
    int mwid = wid & 3, nhalf = wid >> 2;
    int h = blockIdx.x, b = blockIdx.y;

    uint32_t aRowSel = (lid & 7) + ((lid >> 3) & 1) * 8;
    uint32_t aColSel = ((lid >> 4) & 1) * 16;
    uint32_t bRowSel = (lid & 7) + ((lid >> 4) & 1) * 8;
    uint32_t bColSel = ((lid >> 3) & 1) * 16;

    const float4* xb4 = (const float4*)(g_xt + (size_t)b*PIX*CC);

    float acc[32];
#pragma unroll
    for (int i = 0; i < 32; i++) acc[i] = 0.f;

    for (int kk = 0; kk < 9; kk++) {
        __syncthreads();
        { // stage B: 64 rows x 128B (+16B pad), hi & lo — 512 items over 256 thr
            const float4* wh = (const float4*)(g_wrgh + kk*4096);
            const float4* wl = (const float4*)(g_wrgl + kk*4096);
#pragma unroll
            for (int j = t; j < 512; j += 256) {
                int row = j >> 3, seg = j & 7;
                *(float4*)(sm0 + DF_BH + row*144 + seg*16) = wh[j];
                *(float4*)(sm0 + DF_BL + row*144 + seg*16) = wl[j];
            }
        }
        if (t < 128) { // per-px bilinear params (t == px)
            int px = t;
            int pix = h*WW + px;
            float off_y = g_offset[((size_t)(b*18 + 2*kk  ))*PIX + pix];
            float off_x = g_offset[((size_t)(b*18 + 2*kk+1))*PIX + pix];
            float m     = g_mask  [((size_t)(b*9  + kk    ))*PIX + pix];
            int ky = kk/3, kx = kk - ky*3;
            float py  = off_y + (float)(ky + h - 1);
            float pxf = off_x + (float)(kx + px - 1);
            float y0f = floorf(py), x0f = floorf(pxf);
            int y0 = (int)y0f, x0 = (int)x0f;
            int y1 = y0 + 1,   x1 = x0 + 1;
            float wy1 = py - y0f,  wx1 = pxf - x0f;
            float wy0 = 1.f - wy1, wx0 = 1.f - wx1;
            bool vy0 = (y0>=0 && y0<HH), vy1 = (y1>=0 && y1<HH);
            bool vx0 = (x0>=0 && x0<WW), vx1 = (x1>=0 && x1<WW);
            int y0c = min(max(y0,0),HH-1), y1c = min(max(y1,0),HH-1);
            int x0c = min(max(x0,0),WW-1), x1c = min(max(x1,0),WW-1);
            int base = px*8;
            spi[base+0] = (y0c*WW + x0c)*16;
            spi[base+1] = (y0c*WW + x1c)*16;
            spi[base+2] = (y1c*WW + x0c)*16;
            spi[base+3] = (y1c*WW + x1c)*16;
            spf[base+4] = (vy0&&vx0) ? wy0*wx0*m : 0.f;
            spf[base+5] = (vy0&&vx1) ? wy0*wx1*m : 0.f;
            spf[base+6] = (vy1&&vx0) ? wy1*wx0*m : 0.f;
            spf[base+7] = (vy1&&vx1) ? wy1*wx1*m : 0.f;
        }
        __syncthreads();
        // gather: 128px x 16 lanes (4 ch each) = 2048 tasks over 256 thr
#pragma unroll 2
        for (int it = 0; it < 8; it++) {
            int j = it*256 + t;
            int px = j >> 4, lane16 = j & 15;
            int base = px*8;
            int i00 = spi[base+0], i01 = spi[base+1], i10 = spi[base+2], i11 = spi[base+3];
            float g00 = spf[base+4], g01 = spf[base+5], g10 = spf[base+6], g11 = spf[base+7];
            float4 a = xb4[i00 + lane16];
            float4 c = xb4[i01 + lane16];
            float4 d = xb4[i10 + lane16];
            float4 e = xb4[i11 + lane16];
            float v0 = g00*a.x + g01*c.x + g10*d.x + g11*e.x;
            float v1 = g00*a.y + g01*c.y + g10*d.y + g11*e.y;
            float v2 = g00*a.z + g01*c.z + g10*d.z + g11*e.z;
            float v3 = g00*a.w + g01*c.w + g10*d.w + g11*e.w;
            float w0=btrunc(v0), w1=btrunc(v1), w2=btrunc(v2), w3=btrunc(v3);
            uint32_t off = px*144 + lane16*8;
            sts2(sb + DF_AH + off, pk(v0,v1), pk(v2,v3));
            sts2(sb + DF_AL + off, pk(v0-w0,v1-w1), pk(v2-w2,v3-w3));
        }
        __syncthreads();

#pragma unroll
        for (int ks = 0; ks < 4; ks++) {
            uint32_t kcol = ks*32;
            uint32_t bh[8], bl[8], ah[8], al[8];
#pragma unroll
            for (int p = 0; p < 2; p++) {
                uint32_t ba = sb + DF_BH + ((nhalf*2 + p)*16 + bRowSel)*144 + kcol + bColSel;
                ldsm4(bh[p*4+0], bh[p*4+1], bh[p*4+2], bh[p*4+3], ba);
                ldsm4(bl[p*4+0], bl[p*4+1], bl[p*4+2], bl[p*4+3], ba + (DF_BL-DF_BH));
            }
#pragma unroll
            for (int m = 0; m < 2; m++) {
                uint32_t aa = sb + DF_AH + (mwid*32 + m*16 + aRowSel)*144 + kcol + aColSel;
                ldsm4(ah[m*4+0], ah[m*4+1], ah[m*4+2], ah[m*4+3], aa);
                ldsm4(al[m*4+0], al[m*4+1], al[m*4+2], al[m*4+3], aa + (DF_AL-DF_AH));
            }
#pragma unroll
            for (int m = 0; m < 2; m++)
#pragma unroll
            for (int n = 0; n < 4; n++) {
                float* d = acc + (m*4+n)*4;
                uint32_t i0 = (n>>1)*4 + (n&1)*2;
                mma16816(d, ah[m*4+0],ah[m*4+1],ah[m*4+2],ah[m*4+3], bh[i0], bh[i0+1]);
                mma16816(d, al[m*4+0],al[m*4+1],al[m*4+2],al[m*4+3], bh[i0], bh[i0+1]);
                mma16816(d, ah[m*4+0],ah[m*4+1],ah[m*4+2],ah[m*4+3], bl[i0], bl[i0+1]);
            }
        }
    }

    // epilogue
    int g = lid >> 2, tig = lid & 3;
    size_t ob = (size_t)b*64*PIX + (size_t)h*WW;
#pragma unroll
    for (int m = 0; m < 2; m++)
#pragma unroll
    for (int n = 0; n < 4; n++)
#pragma unroll
    for (int r = 0; r < 4; r++) {
        int px = mwid*32 + m*16 + g + (r>>1)*8;
        int oc = nhalf*32 + n*8 + 2*tig + (r&1);
        out[ob + (size_t)oc*PIX + px] = acc[(m*4+n)*4 + r];
    }
}

// ---------------------------------------------------------------------------
extern "C" void kernel_launch(void* const* d_in, const int* in_sizes, int n_in,
                              void* d_out, int out_size)
{
    const float* x     = (const float*)d_in[0];
    const float* guide = (const float*)d_in[1];
    const float* w_off = (const float*)d_in[2];
    const float* b_off = (const float*)d_in[3];
    const float* w_mod = (const float*)d_in[4];
    const float* b_mod = (const float*)d_in[5];
    const float* w_reg = (const float*)d_in[6];
    float* out = (float*)d_out;

    cudaFuncSetAttribute(k_offmod, cudaFuncAttributeMaxDynamicSharedMemorySize, OM_SMEM);
    cudaFuncSetAttribute(k_deform, cudaFuncAttributeMaxDynamicSharedMemorySize, DF_SMEM);

    k_transpose<<<dim3(HH, BB, 2), 256>>>(x, guide);
    k_prepw    <<<144, 256>>>(w_off, w_mod, w_reg);
    k_offmod   <<<dim3(HH, BB), 256, OM_SMEM>>>(b_off, b_mod);
    k_deform   <<<dim3(HH, BB), 256, DF_SMEM>>>(out);
}